// round 3
// baseline (speedup 1.0000x reference)
#include <cuda_runtime.h>
#include <math.h>

// ---------------- problem constants ----------------
constexpr int R    = 4096;   // proposals
constexpr int D    = 4096;   // feature dim
constexpr int C    = 20;     // classes (after dropping last)
constexpr int NC   = 21;     // C + 1
constexpr float IMG_W = 1216.0f;
constexpr float IMG_H = 800.0f;
constexpr float SCORE_THRESH = 0.05f;
constexpr float NMS_THRESH   = 0.5f;
constexpr int TOPK = 100;

// ---------------- GEMM tiling ----------------
constexpr int KSPLIT = 4;
constexpr int BM     = 64;             // rows per block
constexpr int ROWBLOCKS = R / BM;      // 64
constexpr int NPAD   = 48;             // 42 cols padded to 48
constexpr int TM     = 4;
constexpr int TN     = 4;
constexpr int RT     = BM / TM;        // 16
constexpr int CT     = NPAD / TN;      // 12
constexpr int NTH    = RT * CT;        // 192 threads
constexpr int KC     = 32;             // K chunk
constexpr int KPB    = D / KSPLIT;     // 1024 K per block

// ---------------- device scratch (static: no allocs allowed) ----------------
__device__ float g_part[KSPLIT][R * NPAD];   // GEMM partial sums
__device__ float g_cls[R * NC];
__device__ float g_det[R * NC];
__device__ float g_colmax[NC];
__device__ float g_colsum[NC];
__device__ float g_scores[R * C];
__device__ float4 g_bclip[R];
__device__ float g_kept[R * C];
__device__ int   g_ncand;
__device__ float g_cand_val[R * C];
__device__ int   g_cand_idx[R * C];
__device__ int   g_sidx[C][R];
__device__ float g_sval[C][R];
__device__ int   g_sorder[C][R];

// ---------------- helpers ----------------
__device__ __forceinline__ float iou_f(float4 a, float4 b) {
    float areaA = (a.z - a.x) * (a.w - a.y);
    float areaB = (b.z - b.x) * (b.w - b.y);
    float lx = fmaxf(a.x, b.x), ly = fmaxf(a.y, b.y);
    float rx = fminf(a.z, b.z), ry = fminf(a.w, b.w);
    float w = fmaxf(rx - lx, 0.f), h = fmaxf(ry - ly, 0.f);
    float inter = w * h;
    return inter / (areaA + areaB - inter + 1e-9f);
}

// ---------------- kernels ----------------
__global__ void k_init() {
    int i = blockIdx.x * blockDim.x + threadIdx.x;
    if (i < R * C) g_kept[i] = 0.f;
    if (i == 0) g_ncand = 0;
}

// dual GEMM: logits = x @ [W_cls | W_det], K-split partials
__global__ __launch_bounds__(NTH) void k_gemm(const float* __restrict__ x,
                                              const float* __restrict__ Wc,
                                              const float* __restrict__ Wd) {
    __shared__ float xs[KC][BM];
    __shared__ float ws[KC][NPAD];
    const int rb  = blockIdx.x;
    const int ks  = blockIdx.y;
    const int tid = threadIdx.x;
    const int rt  = tid / CT;
    const int ct  = tid % CT;
    const int row0  = rb * BM;
    const int kbase = ks * KPB;

    float acc[TM][TN];
#pragma unroll
    for (int i = 0; i < TM; i++)
#pragma unroll
        for (int j = 0; j < TN; j++) acc[i][j] = 0.f;

    // zero the padded W columns (42..47) once; never overwritten afterwards
    for (int q = tid; q < KC * (NPAD - 2 * NC); q += NTH) {
        int kk = q / (NPAD - 2 * NC);
        int j  = q % (NPAD - 2 * NC);
        ws[kk][2 * NC + j] = 0.f;
    }

    for (int kc = 0; kc < KPB; kc += KC) {
        const int k0 = kbase + kc;
        __syncthreads();
        // stage x chunk transposed: xs[k][row]
        for (int q = tid; q < BM * (KC / 4); q += NTH) {
            int r  = q / (KC / 4);
            int kq = q % (KC / 4);
            float4 v = *reinterpret_cast<const float4*>(
                &x[(size_t)(row0 + r) * D + k0 + kq * 4]);
            xs[kq * 4 + 0][r] = v.x;
            xs[kq * 4 + 1][r] = v.y;
            xs[kq * 4 + 2][r] = v.z;
            xs[kq * 4 + 3][r] = v.w;
        }
        // stage W chunk: cols 0..20 = W_cls, 21..41 = W_det
        for (int q = tid; q < KC * NC; q += NTH) {
            int kk = q / NC;
            int c  = q % NC;
            ws[kk][c]      = Wc[(size_t)(k0 + kk) * NC + c];
            ws[kk][NC + c] = Wd[(size_t)(k0 + kk) * NC + c];
        }
        __syncthreads();
#pragma unroll 8
        for (int kk = 0; kk < KC; kk++) {
            float4 xv = *reinterpret_cast<const float4*>(&xs[kk][rt * TM]);
            float4 wv = *reinterpret_cast<const float4*>(&ws[kk][ct * TN]);
            float xr[4] = {xv.x, xv.y, xv.z, xv.w};
            float wr[4] = {wv.x, wv.y, wv.z, wv.w};
#pragma unroll
            for (int i = 0; i < TM; i++)
#pragma unroll
                for (int j = 0; j < TN; j++)
                    acc[i][j] = fmaf(xr[i], wr[j], acc[i][j]);
        }
    }
    float* dst = &g_part[ks][0];
#pragma unroll
    for (int i = 0; i < TM; i++) {
        int row = row0 + rt * TM + i;
#pragma unroll
        for (int j = 0; j < TN; j++)
            dst[(size_t)row * NPAD + ct * TN + j] = acc[i][j];
    }
}

// combine K-split partials + bias -> cls/det logits
__global__ void k_reduce(const float* __restrict__ b_cls,
                         const float* __restrict__ b_det) {
    int i = blockIdx.x * blockDim.x + threadIdx.x;
    if (i >= R * 2 * NC) return;
    int row = i / (2 * NC);
    int c   = i % (2 * NC);
    float s = 0.f;
#pragma unroll
    for (int ks = 0; ks < KSPLIT; ks++) s += g_part[ks][(size_t)row * NPAD + c];
    if (c < NC) g_cls[row * NC + c] = s + b_cls[c];
    else        g_det[row * NC + (c - NC)] = s + b_det[c - NC];
}

// column softmax stats for det logits (softmax over rows, per column)
__global__ __launch_bounds__(256) void k_colred() {
    __shared__ float red[256];
    const int c   = blockIdx.x;
    const int tid = threadIdx.x;
    float m = -1e30f;
    for (int r = tid; r < R; r += 256) m = fmaxf(m, g_det[r * NC + c]);
    red[tid] = m; __syncthreads();
    for (int s = 128; s > 0; s >>= 1) {
        if (tid < s) red[tid] = fmaxf(red[tid], red[tid + s]);
        __syncthreads();
    }
    m = red[0]; __syncthreads();
    float sum = 0.f;
    for (int r = tid; r < R; r += 256) sum += expf(g_det[r * NC + c] - m);
    red[tid] = sum; __syncthreads();
    for (int s = 128; s > 0; s >>= 1) {
        if (tid < s) red[tid] += red[tid + s];
        __syncthreads();
    }
    if (tid == 0) { g_colmax[c] = m; g_colsum[c] = red[0]; }
}

// scores = row_softmax(cls) * col_softmax(det), drop last col; clip boxes
__global__ __launch_bounds__(256) void k_scores(const float* __restrict__ boxes) {
    int row = blockIdx.x * blockDim.x + threadIdx.x;
    if (row >= R) return;
    float cl[NC];
    float rm = -1e30f;
#pragma unroll
    for (int c = 0; c < NC; c++) {
        cl[c] = g_cls[row * NC + c];
        rm = fmaxf(rm, cl[c]);
    }
    float rs = 0.f;
#pragma unroll
    for (int c = 0; c < NC; c++) { cl[c] = expf(cl[c] - rm); rs += cl[c]; }
    float inv = 1.f / rs;
#pragma unroll
    for (int c = 0; c < C; c++) {
        float det = expf(g_det[row * NC + c] - g_colmax[c]) / g_colsum[c];
        g_scores[row * C + c] = cl[c] * inv * det;
    }
    float x1 = fminf(fmaxf(boxes[row * 4 + 0], 0.f), IMG_W);
    float y1 = fminf(fmaxf(boxes[row * 4 + 1], 0.f), IMG_H);
    float x2 = fminf(fmaxf(boxes[row * 4 + 2], 0.f), IMG_W);
    float y2 = fminf(fmaxf(boxes[row * 4 + 3], 0.f), IMG_H);
    g_bclip[row] = make_float4(x1, y1, x2, y2);
}

// per-class greedy NMS (one block per class)
__global__ __launch_bounds__(256) void k_nms() {
    __shared__ int scnt;
    __shared__ unsigned char ssupp[R];
    const int cls = blockIdx.x;
    const int tid = threadIdx.x;
    if (tid == 0) scnt = 0;
    __syncthreads();
    // gather candidates above the score threshold
    for (int r = tid; r < R; r += 256) {
        float v = g_scores[r * C + cls];
        if (v > SCORE_THRESH) {
            int p = atomicAdd(&scnt, 1);
            g_sidx[cls][p] = r;
            g_sval[cls][p] = v;
        }
    }
    __syncthreads();
    const int m = scnt;
    if (m == 0) return;
    // rank sort: descending score, tie -> lower proposal index (argsort(-sc) stable)
    for (int i = tid; i < m; i += 256) {
        float vi = g_sval[cls][i];
        int   ri = g_sidx[cls][i];
        int rank = 0;
        for (int j = 0; j < m; j++) {
            float vj = g_sval[cls][j];
            int   rj = g_sidx[cls][j];
            if (vj > vi || (vj == vi && rj < ri)) rank++;
        }
        g_sorder[cls][rank] = i;
    }
    for (int q = tid; q < m; q += 256) ssupp[q] = 0;
    __syncthreads();
    // sequential greedy with parallel suppression
    for (int pos = 0; pos < m; pos++) {
        if (!ssupp[pos]) {
            int   i = g_sorder[cls][pos];
            int   r = g_sidx[cls][i];
            float v = g_sval[cls][i];
            if (tid == 0) {
                g_kept[r * C + cls] = v;
                int p = atomicAdd(&g_ncand, 1);
                g_cand_val[p] = v;
                g_cand_idx[p] = r * C + cls;
            }
            float4 bi = g_bclip[r];
            for (int q = pos + 1 + tid; q < m; q += 256) {
                if (!ssupp[q]) {
                    int j = g_sorder[cls][q];
                    float4 bj = g_bclip[g_sidx[cls][j]];
                    if (iou_f(bi, bj) > NMS_THRESH) ssupp[q] = 1;
                }
            }
        }
        __syncthreads();
    }
}

// top-100 with jax.lax.top_k tie semantics; output = [vals | boxes | cls]
__global__ __launch_bounds__(256) void k_final(float* __restrict__ out) {
    __shared__ float bv[256];
    __shared__ int   bfi[256];
    __shared__ int   bps[256];
    const int tid = threadIdx.x;
    int n = g_ncand;
    if (n > R * C) n = R * C;
    int take = n < TOPK ? n : TOPK;
    for (int round = 0; round < take; round++) {
        float best = -2.f; int bestfi = 0x7fffffff; int bestp = -1;
        for (int p = tid; p < n; p += 256) {
            float v = g_cand_val[p];
            if (v < 0.f) continue;  // already taken
            int fi = g_cand_idx[p];
            if (v > best || (v == best && fi < bestfi)) {
                best = v; bestfi = fi; bestp = p;
            }
        }
        bv[tid] = best; bfi[tid] = bestfi; bps[tid] = bestp;
        __syncthreads();
        for (int s = 128; s > 0; s >>= 1) {
            if (tid < s) {
                if (bv[tid + s] > bv[tid] ||
                    (bv[tid + s] == bv[tid] && bfi[tid + s] < bfi[tid])) {
                    bv[tid] = bv[tid + s];
                    bfi[tid] = bfi[tid + s];
                    bps[tid] = bps[tid + s];
                }
            }
            __syncthreads();
        }
        if (tid == 0) {
            int fi = bfi[0];
            int prop = fi / C, cl = fi % C;
            float4 b = g_bclip[prop];
            out[round] = bv[0];
            out[TOPK + round * 4 + 0] = b.x;
            out[TOPK + round * 4 + 1] = b.y;
            out[TOPK + round * 4 + 2] = b.z;
            out[TOPK + round * 4 + 3] = b.w;
            out[TOPK + TOPK * 4 + round] = (float)cl;
            g_cand_val[bps[0]] = -1.f;
        }
        __syncthreads();
    }
    // fill remaining slots with zeros: lowest flat indices among non-kept
    if (tid == 0) {
        int slot = take;
        int i = 0;
        while (slot < TOPK && i < R * C) {
            if (g_kept[i] == 0.f) {
                int prop = i / C, cl = i % C;
                float4 b = g_bclip[prop];
                out[slot] = 0.f;
                out[TOPK + slot * 4 + 0] = b.x;
                out[TOPK + slot * 4 + 1] = b.y;
                out[TOPK + slot * 4 + 2] = b.z;
                out[TOPK + slot * 4 + 3] = b.w;
                out[TOPK + TOPK * 4 + slot] = (float)cl;
                slot++;
            }
            i++;
        }
    }
}

extern "C" void kernel_launch(void* const* d_in, const int* in_sizes, int n_in,
                              void* d_out, int out_size) {
    const float* x     = (const float*)d_in[0];
    const float* boxes = (const float*)d_in[1];
    const float* W_cls = (const float*)d_in[2];
    const float* b_cls = (const float*)d_in[3];
    const float* W_det = (const float*)d_in[4];
    const float* b_det = (const float*)d_in[5];
    float* out = (float*)d_out;

    k_init<<<(R * C + 255) / 256, 256>>>();
    dim3 gg(ROWBLOCKS, KSPLIT);
    k_gemm<<<gg, NTH>>>(x, W_cls, W_det);
    k_reduce<<<(R * 2 * NC + 255) / 256, 256>>>(b_cls, b_det);
    k_colred<<<NC, 256>>>();
    k_scores<<<(R + 255) / 256, 256>>>(boxes);
    k_nms<<<C, 256>>>();
    k_final<<<1, 256>>>(out);
}

// round 4
// speedup vs baseline: 1.3266x; 1.3266x over previous
#include <cuda_runtime.h>
#include <math.h>

// ---------------- problem constants ----------------
constexpr int R    = 4096;
constexpr int D    = 4096;
constexpr int C    = 20;
constexpr int NC   = 21;
constexpr float IMG_W = 1216.0f;
constexpr float IMG_H = 800.0f;
constexpr float SCORE_THRESH = 0.05f;
constexpr float NMS_THRESH   = 0.5f;
constexpr int TOPK = 100;

// ---------------- GEMM tiling ----------------
constexpr int KSPLIT  = 8;
constexpr int BM      = 64;
constexpr int ROWBLOCKS = R / BM;       // 64
constexpr int NPAD    = 48;             // 42 -> 48
constexpr int TM      = 4;
constexpr int TN      = 4;
constexpr int RT      = BM / TM;        // 16
constexpr int CT      = NPAD / TN;      // 12
constexpr int NTH     = RT * CT;        // 192
constexpr int KC      = 32;
constexpr int KPB     = D / KSPLIT;     // 512
constexpr int NCHUNKS = KPB / KC;       // 16
constexpr int XS_W    = 66;             // padded float2 row (bank-conflict fix, 16B-aligned)

// ---------------- device scratch ----------------
__device__ float g_part[KSPLIT][R * NPAD];
__device__ float g_cls[R * NC];
__device__ float g_det[R * C];          // exp(det logit), cols 0..19 only needed
__device__ float g_colpart[ROWBLOCKS][NC];
__device__ float g_colsum[NC];
__device__ float g_scoresT[C * R];      // transposed for coalesced NMS
__device__ float4 g_bclip[R];
__device__ float g_kept[R * C];
__device__ int   g_ncand;
__device__ float g_cand_val[R * C];
__device__ int   g_cand_idx[R * C];
__device__ int   g_sidx[C][R];
__device__ float g_sval[C][R];
__device__ int   g_sorder[C][R];

// ---------------- helpers ----------------
union U64F2 { unsigned long long u; float2 f; };

__device__ __forceinline__ unsigned long long fma2(unsigned long long a,
                                                   unsigned long long b,
                                                   unsigned long long c) {
    unsigned long long d;
    asm("fma.rn.f32x2 %0, %1, %2, %3;" : "=l"(d) : "l"(a), "l"(b), "l"(c));
    return d;
}

__device__ __forceinline__ float iou_f(float4 a, float4 b) {
    float areaA = (a.z - a.x) * (a.w - a.y);
    float areaB = (b.z - b.x) * (b.w - b.y);
    float lx = fmaxf(a.x, b.x), ly = fmaxf(a.y, b.y);
    float rx = fminf(a.z, b.z), ry = fminf(a.w, b.w);
    float w = fmaxf(rx - lx, 0.f), h = fmaxf(ry - ly, 0.f);
    float inter = w * h;
    return inter / (areaA + areaB - inter + 1e-9f);
}

// ---------------- GEMM: logits = x @ [W_cls | W_det], f32x2 packed FMA ----------------
__global__ __launch_bounds__(NTH) void k_gemm(const float* __restrict__ x,
                                              const float* __restrict__ Wc,
                                              const float* __restrict__ Wd) {
    // xs2: x values duplicated as (v,v) pairs, [k][row]
    // ws : W column pairs (natural packing), 48 floats per k row (42 data + 6 pad)
    __shared__ __align__(16) float2 xs2[2][KC][XS_W];
    __shared__ __align__(16) float2 ws[2][KC][NPAD / 2];

    const int rb  = blockIdx.x;
    const int ks  = blockIdx.y;
    const int tid = threadIdx.x;
    const int rt  = tid / CT;
    const int ct  = tid % CT;
    const int row0  = rb * BM;
    const int kbase = ks * KPB;

    // zero W pad cols (42..47) in both buffers; never overwritten afterwards
    for (int q = tid; q < 2 * KC * 3; q += NTH) {
        int b = q / (KC * 3);
        int r = q % (KC * 3);
        ws[b][r / 3][21 + (r % 3)] = make_float2(0.f, 0.f);
    }

    unsigned long long acc[TM][TN / 2];
#pragma unroll
    for (int i = 0; i < TM; i++)
#pragma unroll
        for (int j = 0; j < TN / 2; j++) acc[i][j] = 0ull;

    float4 xr[3];
    float  wr[7];

    auto ldg_chunk = [&](int k0) {
#pragma unroll
        for (int it = 0; it < 3; it++) {
            int q = it * NTH + tid;
            if (q < BM * KC / 4) {
                int r  = q >> 3;
                int kq = q & 7;
                xr[it] = *reinterpret_cast<const float4*>(
                    &x[(size_t)(row0 + r) * D + k0 + kq * 4]);
            }
        }
#pragma unroll
        for (int it = 0; it < 7; it++) {
            int q  = it * NTH + tid;          // 0..1343
            int m  = q / (KC * NC);           // 0 = cls, 1 = det
            int qq = q - m * (KC * NC);       // contiguous within each matrix
            const float* src = m ? Wd : Wc;
            wr[it] = src[(size_t)k0 * NC + qq];
        }
    };

    auto sts_chunk = [&](int buf) {
#pragma unroll
        for (int it = 0; it < 3; it++) {
            int q = it * NTH + tid;
            if (q < BM * KC / 4) {
                int r  = q >> 3;
                int kq = q & 7;
                float4 v = xr[it];
                xs2[buf][kq * 4 + 0][r] = make_float2(v.x, v.x);
                xs2[buf][kq * 4 + 1][r] = make_float2(v.y, v.y);
                xs2[buf][kq * 4 + 2][r] = make_float2(v.z, v.z);
                xs2[buf][kq * 4 + 3][r] = make_float2(v.w, v.w);
            }
        }
#pragma unroll
        for (int it = 0; it < 7; it++) {
            int q  = it * NTH + tid;
            int m  = q / (KC * NC);
            int qq = q - m * (KC * NC);
            int kk = qq / NC;
            int c  = qq - kk * NC;
            reinterpret_cast<float*>(&ws[buf][kk][0])[m * NC + c] = wr[it];
        }
    };

    ldg_chunk(kbase);
    int buf = 0;
    for (int ch = 0; ch < NCHUNKS; ch++) {
        sts_chunk(buf);
        __syncthreads();
        if (ch + 1 < NCHUNKS) ldg_chunk(kbase + (ch + 1) * KC);
#pragma unroll 8
        for (int kk = 0; kk < KC; kk++) {
            ulonglong2 x01 = *reinterpret_cast<const ulonglong2*>(&xs2[buf][kk][rt * TM]);
            ulonglong2 x23 = *reinterpret_cast<const ulonglong2*>(&xs2[buf][kk][rt * TM + 2]);
            ulonglong2 wv  = *reinterpret_cast<const ulonglong2*>(&ws[buf][kk][ct * (TN / 2)]);
            acc[0][0] = fma2(x01.x, wv.x, acc[0][0]);
            acc[0][1] = fma2(x01.x, wv.y, acc[0][1]);
            acc[1][0] = fma2(x01.y, wv.x, acc[1][0]);
            acc[1][1] = fma2(x01.y, wv.y, acc[1][1]);
            acc[2][0] = fma2(x23.x, wv.x, acc[2][0]);
            acc[2][1] = fma2(x23.x, wv.y, acc[2][1]);
            acc[3][0] = fma2(x23.y, wv.x, acc[3][0]);
            acc[3][1] = fma2(x23.y, wv.y, acc[3][1]);
        }
        __syncthreads();
        buf ^= 1;
    }

#pragma unroll
    for (int i = 0; i < TM; i++) {
        int row = row0 + rt * TM + i;
        U64F2 a0, a1;
        a0.u = acc[i][0];
        a1.u = acc[i][1];
        *reinterpret_cast<float4*>(&g_part[ks][(size_t)row * NPAD + ct * TN]) =
            make_float4(a0.f.x, a0.f.y, a1.f.x, a1.f.y);
    }
}

// ---------------- reduce partials + bias; exp(det); deterministic colsum partials ----------------
__global__ __launch_bounds__(256) void k_reduce(const float* __restrict__ b_cls,
                                                const float* __restrict__ b_det) {
    __shared__ float scol[8][NC];
    const int tid = threadIdx.x;
    if (tid < 8 * NC) scol[tid / NC][tid % NC] = 0.f;
    __syncthreads();
    const int row0 = blockIdx.x * BM;
    const int wid = tid >> 5;
    for (int q = tid; q < BM * 2 * NC; q += 256) {
        int lr  = q / (2 * NC);
        int c   = q % (2 * NC);
        int row = row0 + lr;
        float s = 0.f;
#pragma unroll
        for (int ks = 0; ks < KSPLIT; ks++) s += g_part[ks][(size_t)row * NPAD + c];
        if (c < NC) {
            g_cls[row * NC + c] = s + b_cls[c];
        } else {
            int cd = c - NC;
            float e = expf(s + b_det[cd]);
            if (cd < C) g_det[row * C + cd] = e;
            // within a warp, 32 consecutive q -> distinct c (32 < 42): no intra-warp RMW race
            scol[wid][cd] += e;
        }
    }
    __syncthreads();
    if (tid < NC) {
        float s = 0.f;
#pragma unroll
        for (int w = 0; w < 8; w++) s += scol[w][tid];
        g_colpart[blockIdx.x][tid] = s;
    }
}

// combine 64 column partials -> g_colsum (1 block, 21 warps)
__global__ __launch_bounds__(672) void k_colfin() {
    int w = threadIdx.x >> 5;
    int lane = threadIdx.x & 31;
    if (w >= NC) return;
    float s = g_colpart[lane][w] + g_colpart[lane + 32][w];
#pragma unroll
    for (int o = 16; o > 0; o >>= 1) s += __shfl_down_sync(0xffffffff, s, o);
    if (lane == 0) g_colsum[w] = s;
}

// scores = row_softmax(cls) * exp(det)/colsum; clip boxes; reset kept/ncand
__global__ __launch_bounds__(256) void k_scores(const float* __restrict__ boxes) {
    int row = blockIdx.x * blockDim.x + threadIdx.x;
    if (row >= R) return;
    float cl[NC];
    float rm = -1e30f;
#pragma unroll
    for (int c = 0; c < NC; c++) {
        cl[c] = g_cls[row * NC + c];
        rm = fmaxf(rm, cl[c]);
    }
    float rs = 0.f;
#pragma unroll
    for (int c = 0; c < NC; c++) { cl[c] = expf(cl[c] - rm); rs += cl[c]; }
    float inv = 1.f / rs;
#pragma unroll
    for (int c = 0; c < C; c++) {
        float detp = g_det[row * C + c] / g_colsum[c];
        g_scoresT[c * R + row] = cl[c] * inv * detp;
        g_kept[row * C + c] = 0.f;
    }
    float x1 = fminf(fmaxf(boxes[row * 4 + 0], 0.f), IMG_W);
    float y1 = fminf(fmaxf(boxes[row * 4 + 1], 0.f), IMG_H);
    float x2 = fminf(fmaxf(boxes[row * 4 + 2], 0.f), IMG_W);
    float y2 = fminf(fmaxf(boxes[row * 4 + 3], 0.f), IMG_H);
    g_bclip[row] = make_float4(x1, y1, x2, y2);
    if (row == 0) g_ncand = 0;
}

// per-class greedy NMS (one block per class)
__global__ __launch_bounds__(256) void k_nms() {
    __shared__ int scnt;
    __shared__ unsigned char ssupp[R];
    const int cls = blockIdx.x;
    const int tid = threadIdx.x;
    if (tid == 0) scnt = 0;
    __syncthreads();
    for (int r = tid; r < R; r += 256) {
        float v = g_scoresT[cls * R + r];
        if (v > SCORE_THRESH) {
            int p = atomicAdd(&scnt, 1);
            g_sidx[cls][p] = r;
            g_sval[cls][p] = v;
        }
    }
    __syncthreads();
    const int m = scnt;
    if (m == 0) return;
    // rank sort: desc score, tie -> lower proposal index
    for (int i = tid; i < m; i += 256) {
        float vi = g_sval[cls][i];
        int   ri = g_sidx[cls][i];
        int rank = 0;
        for (int j = 0; j < m; j++) {
            float vj = g_sval[cls][j];
            int   rj = g_sidx[cls][j];
            if (vj > vi || (vj == vi && rj < ri)) rank++;
        }
        g_sorder[cls][rank] = i;
    }
    for (int q = tid; q < m; q += 256) ssupp[q] = 0;
    __syncthreads();
    for (int pos = 0; pos < m; pos++) {
        if (!ssupp[pos]) {
            int   i = g_sorder[cls][pos];
            int   r = g_sidx[cls][i];
            float v = g_sval[cls][i];
            if (tid == 0) {
                g_kept[r * C + cls] = v;
                int p = atomicAdd(&g_ncand, 1);
                g_cand_val[p] = v;
                g_cand_idx[p] = r * C + cls;
            }
            float4 bi = g_bclip[r];
            for (int q = pos + 1 + tid; q < m; q += 256) {
                if (!ssupp[q]) {
                    int j = g_sorder[cls][q];
                    float4 bj = g_bclip[g_sidx[cls][j]];
                    if (iou_f(bi, bj) > NMS_THRESH) ssupp[q] = 1;
                }
            }
        }
        __syncthreads();
    }
}

// top-100 (jax.lax.top_k tie semantics) + parallel zero-fill
__global__ __launch_bounds__(256) void k_final(float* __restrict__ out) {
    __shared__ float bv[256];
    __shared__ int   bfi[256];
    __shared__ int   bps[256];
    __shared__ int   s_base;
    __shared__ int   s_woff[8];
    const int tid = threadIdx.x;
    int n = g_ncand;
    if (n > R * C) n = R * C;
    int take = n < TOPK ? n : TOPK;
    for (int round = 0; round < take; round++) {
        float best = -2.f; int bestfi = 0x7fffffff; int bestp = -1;
        for (int p = tid; p < n; p += 256) {
            float v = g_cand_val[p];
            if (v < 0.f) continue;
            int fi = g_cand_idx[p];
            if (v > best || (v == best && fi < bestfi)) {
                best = v; bestfi = fi; bestp = p;
            }
        }
        bv[tid] = best; bfi[tid] = bestfi; bps[tid] = bestp;
        __syncthreads();
        for (int s = 128; s > 0; s >>= 1) {
            if (tid < s) {
                if (bv[tid + s] > bv[tid] ||
                    (bv[tid + s] == bv[tid] && bfi[tid + s] < bfi[tid])) {
                    bv[tid] = bv[tid + s];
                    bfi[tid] = bfi[tid + s];
                    bps[tid] = bps[tid + s];
                }
            }
            __syncthreads();
        }
        if (tid == 0) {
            int fi = bfi[0];
            int prop = fi / C, cl = fi % C;
            float4 b = g_bclip[prop];
            out[round] = bv[0];
            out[TOPK + round * 4 + 0] = b.x;
            out[TOPK + round * 4 + 1] = b.y;
            out[TOPK + round * 4 + 2] = b.z;
            out[TOPK + round * 4 + 3] = b.w;
            out[TOPK + TOPK * 4 + round] = (float)cl;
            g_cand_val[bps[0]] = -1.f;
        }
        __syncthreads();
    }
    // parallel zero-fill: lowest flat indices among non-kept entries
    if (tid == 0) s_base = take;
    __syncthreads();
    for (int chunk = 0; chunk < R * C; chunk += 256) {
        if (s_base >= TOPK) break;
        int e = chunk + tid;
        bool f = (g_kept[e] == 0.f);
        unsigned bal = __ballot_sync(0xffffffff, f);
        if ((tid & 31) == 0) s_woff[tid >> 5] = __popc(bal);
        __syncthreads();
        int pre = 0;
#pragma unroll
        for (int w = 0; w < 8; w++)
            if (w < (tid >> 5)) pre += s_woff[w];
        int rank = pre + __popc(bal & ((1u << (tid & 31)) - 1u));
        int slot = s_base + rank;
        if (f && slot < TOPK) {
            int prop = e / C, cl = e % C;
            float4 b = g_bclip[prop];
            out[slot] = 0.f;
            out[TOPK + slot * 4 + 0] = b.x;
            out[TOPK + slot * 4 + 1] = b.y;
            out[TOPK + slot * 4 + 2] = b.z;
            out[TOPK + slot * 4 + 3] = b.w;
            out[TOPK + TOPK * 4 + slot] = (float)cl;
        }
        __syncthreads();
        if (tid == 0) {
            int tot = 0;
#pragma unroll
            for (int w = 0; w < 8; w++) tot += s_woff[w];
            s_base += tot;
            if (s_base > TOPK) s_base = TOPK;
        }
        __syncthreads();
    }
}

extern "C" void kernel_launch(void* const* d_in, const int* in_sizes, int n_in,
                              void* d_out, int out_size) {
    const float* x     = (const float*)d_in[0];
    const float* boxes = (const float*)d_in[1];
    const float* W_cls = (const float*)d_in[2];
    const float* b_cls = (const float*)d_in[3];
    const float* W_det = (const float*)d_in[4];
    const float* b_det = (const float*)d_in[5];
    float* out = (float*)d_out;

    dim3 gg(ROWBLOCKS, KSPLIT);
    k_gemm<<<gg, NTH>>>(x, W_cls, W_det);
    k_reduce<<<ROWBLOCKS, 256>>>(b_cls, b_det);
    k_colfin<<<1, 672>>>();
    k_scores<<<R / 256, 256>>>(boxes);
    k_nms<<<C, 256>>>();
    k_final<<<1, 256>>>(out);
}

// round 6
// speedup vs baseline: 3.4615x; 2.6093x over previous
#include <cuda_runtime.h>
#include <cuda_bf16.h>
#include <math.h>
#include <stdint.h>

// ---------------- problem constants ----------------
constexpr int R    = 4096;
constexpr int D    = 4096;
constexpr int C    = 20;
constexpr int NC   = 21;
constexpr float IMG_W = 1216.0f;
constexpr float IMG_H = 800.0f;
constexpr float SCORE_THRESH = 0.05f;
constexpr float NMS_THRESH   = 0.5f;
constexpr int TOPK = 100;
constexpr int NPAD = 48;                 // 42 logit cols padded to 48

// ---------------- mma GEMM config ----------------
constexpr int BMG = 128;                 // M per CTA
constexpr int GRB = R / BMG;             // 32 row blocks
constexpr int GKS = 8;                   // K split
constexpr int KPB = D / GKS;             // 512 K per CTA
constexpr int KC  = 64;                  // K per A chunk
constexpr int NCH = KPB / KC;            // 8 chunks
constexpr int GTH = 256;                 // 8 warps

// dynamic smem layout (bytes)
constexpr int RS_B   = 1040;             // 512 bf16 = 1024B + 16 pad
constexpr int RS_A   = 144;              // 64 bf16 = 128B + 16 pad
constexpr int SM_B   = 0;
constexpr int SM_A   = NPAD * RS_B;      // 49920
constexpr int A_BYTES = BMG * RS_A;      // 18432
constexpr int SM_TOTAL = SM_A + 2 * A_BYTES;   // 86784

// ---------------- device scratch ----------------
__device__ __nv_bfloat16 g_WbfT[NPAD * D];   // W transposed+padded, bf16, [n][k]
__device__ float g_part[GKS][R * NPAD];
__device__ float g_cls[R * NC];
__device__ float g_det[R * C];               // exp(det logit)
__device__ float g_colpart[64][NC];
__device__ float g_colsum[NC];
__device__ float g_scoresT[C * R];
__device__ float4 g_bclip[R];
__device__ float g_kept[R * C];
__device__ int   g_ncand;
__device__ float g_cand_val[R * C];
__device__ int   g_cand_idx[R * C];
__device__ int   g_sidx[C][R];
__device__ float g_sval[C][R];
__device__ int   g_sorder[C][R];

// ---------------- helpers ----------------
__device__ __forceinline__ uint32_t pack_bf2(float lo, float hi) {
    __nv_bfloat162 h = __floats2bfloat162_rn(lo, hi);  // .x (low half) = lo
    return *reinterpret_cast<uint32_t*>(&h);
}

#define CP16(dst, src) \
    asm volatile("cp.async.ca.shared.global [%0], [%1], 16;" :: "r"(dst), "l"(src))
#define CP_COMMIT() asm volatile("cp.async.commit_group;" ::: "memory")
#define CP_WAIT0()  asm volatile("cp.async.wait_group 0;" ::: "memory")

__device__ __forceinline__ uint32_t smem_u32(const void* p) {
    uint32_t a;
    asm("{ .reg .u64 t; cvta.to.shared.u64 t, %1; cvt.u32.u64 %0, t; }" : "=r"(a) : "l"(p));
    return a;
}

__device__ __forceinline__ void mma_bf16(float* c, uint32_t a0, uint32_t a1,
                                         uint32_t a2, uint32_t a3,
                                         uint32_t b0, uint32_t b1) {
    asm volatile(
        "mma.sync.aligned.m16n8k16.row.col.f32.bf16.bf16.f32 "
        "{%0,%1,%2,%3}, {%4,%5,%6,%7}, {%8,%9}, {%0,%1,%2,%3};"
        : "+f"(c[0]), "+f"(c[1]), "+f"(c[2]), "+f"(c[3])
        : "r"(a0), "r"(a1), "r"(a2), "r"(a3), "r"(b0), "r"(b1));
}

__device__ __forceinline__ uint32_t lds_u32(uint32_t addr) {
    uint32_t v;
    asm volatile("ld.shared.b32 %0, [%1];" : "=r"(v) : "r"(addr));
    return v;
}

__device__ __forceinline__ float iou_f(float4 a, float4 b) {
    float areaA = (a.z - a.x) * (a.w - a.y);
    float areaB = (b.z - b.x) * (b.w - b.y);
    float lx = fmaxf(a.x, b.x), ly = fmaxf(a.y, b.y);
    float rx = fminf(a.z, b.z), ry = fminf(a.w, b.w);
    float w = fmaxf(rx - lx, 0.f), h = fmaxf(ry - ly, 0.f);
    float inter = w * h;
    return inter / (areaA + areaB - inter + 1e-9f);
}

// ---------------- W -> transposed bf16 [48][4096] ----------------
__global__ __launch_bounds__(256) void k_prep(const float* __restrict__ Wc,
                                              const float* __restrict__ Wd) {
    int idx = blockIdx.x * 256 + threadIdx.x;   // n * 2048 + kw
    if (idx >= NPAD * (D / 2)) return;
    int n  = idx >> 11;
    int kw = idx & 2047;
    float f0 = 0.f, f1 = 0.f;
    if (n < 21) {
        f0 = Wc[(size_t)(2 * kw) * NC + n];
        f1 = Wc[(size_t)(2 * kw + 1) * NC + n];
    } else if (n < 42) {
        f0 = Wd[(size_t)(2 * kw) * NC + (n - 21)];
        f1 = Wd[(size_t)(2 * kw + 1) * NC + (n - 21)];
    }
    reinterpret_cast<uint32_t*>(g_WbfT)[idx] = pack_bf2(f0, f1);
}

// ---------------- GEMM: bf16 mma.sync m16n8k16 ----------------
__global__ __launch_bounds__(GTH, 2) void k_gemm(const float* __restrict__ x) {
    extern __shared__ char smem[];
    const uint32_t sb = smem_u32(smem);
    const int tid  = threadIdx.x;
    const int w    = tid >> 5;
    const int lane = tid & 31;
    const int g = lane >> 2;
    const int t = lane & 3;
    const int row0  = blockIdx.x * BMG;
    const int kbase = blockIdx.y * KPB;

    // stage B (whole 512-K slice, pre-converted bf16) via cp.async
#pragma unroll
    for (int it = 0; it < 12; it++) {
        int q = tid + it * GTH;                 // < 3072
        int n = q >> 6, seg = q & 63;
        CP16(sb + SM_B + n * RS_B + seg * 16,
             reinterpret_cast<const char*>(g_WbfT) +
                 ((size_t)n * D + kbase) * 2 + seg * 16);
    }
    CP_COMMIT();

    float acc[6][4];
#pragma unroll
    for (int nt = 0; nt < 6; nt++)
#pragma unroll
        for (int j = 0; j < 4; j++) acc[nt][j] = 0.f;

    float4 xr[8];
    auto ldgA = [&](int ch) {
        const int k0 = kbase + ch * KC;
#pragma unroll
        for (int it = 0; it < 8; it++) {
            int q = tid + it * GTH;             // < 2048
            int r = q >> 4, quad = q & 15;
            xr[it] = *reinterpret_cast<const float4*>(
                &x[(size_t)(row0 + r) * D + k0 + quad * 4]);
        }
    };
    auto stsA = [&](int buf) {
        const uint32_t ab = sb + SM_A + buf * A_BYTES;
#pragma unroll
        for (int it = 0; it < 8; it++) {
            int q = tid + it * GTH;
            int r = q >> 4, quad = q & 15;
            uint2 v = make_uint2(pack_bf2(xr[it].x, xr[it].y),
                                 pack_bf2(xr[it].z, xr[it].w));
            asm volatile("st.shared.v2.b32 [%0], {%1, %2};"
                         :: "r"(ab + r * RS_A + quad * 8), "r"(v.x), "r"(v.y));
        }
    };

    ldgA(0);
    const uint32_t a_base0 = sb + SM_A + (w * 16 + g) * RS_A + t * 4;
    const uint32_t b_base  = sb + SM_B + g * RS_B + t * 4;

    for (int ch = 0; ch < NCH; ch++) {
        const int buf = ch & 1;
        stsA(buf);
        if (ch == 0) CP_WAIT0();
        __syncthreads();
        if (ch + 1 < NCH) ldgA(ch + 1);
        const uint32_t ab = a_base0 + buf * A_BYTES;
#pragma unroll
        for (int ks = 0; ks < 4; ks++) {
            const uint32_t ao = ab + ks * 32;
            uint32_t a0 = lds_u32(ao);
            uint32_t a1 = lds_u32(ao + 8 * RS_A);
            uint32_t a2 = lds_u32(ao + 16);
            uint32_t a3 = lds_u32(ao + 8 * RS_A + 16);
            const uint32_t bo0 = b_base + ch * 128 + ks * 32;
#pragma unroll
            for (int nt = 0; nt < 6; nt++) {
                uint32_t bo = bo0 + nt * 8 * RS_B;
                uint32_t b0 = lds_u32(bo);
                uint32_t b1 = lds_u32(bo + 16);
                mma_bf16(acc[nt], a0, a1, a2, a3, b0, b1);
            }
        }
        __syncthreads();
    }

    // epilogue: D frag -> g_part[blockIdx.y]
    float* dst = &g_part[blockIdx.y][0];
    int row = row0 + w * 16 + g;
#pragma unroll
    for (int nt = 0; nt < 6; nt++) {
        int col = nt * 8 + 2 * t;
        *reinterpret_cast<float2*>(&dst[(size_t)row * NPAD + col]) =
            make_float2(acc[nt][0], acc[nt][1]);
        *reinterpret_cast<float2*>(&dst[(size_t)(row + 8) * NPAD + col]) =
            make_float2(acc[nt][2], acc[nt][3]);
    }
}

// ---------------- reduce partials + bias; exp(det); colsum partials ----------------
__global__ __launch_bounds__(256) void k_reduce(const float* __restrict__ b_cls,
                                                const float* __restrict__ b_det) {
    __shared__ float scol[8][NC];
    const int tid = threadIdx.x;
    if (tid < 8 * NC) scol[tid / NC][tid % NC] = 0.f;
    __syncthreads();
    const int row0 = blockIdx.x * 64;
    const int wid = tid >> 5;
    for (int q = tid; q < 64 * 2 * NC; q += 256) {
        int lr  = q / (2 * NC);
        int c   = q % (2 * NC);
        int row = row0 + lr;
        float s = 0.f;
#pragma unroll
        for (int ks = 0; ks < GKS; ks++) s += g_part[ks][(size_t)row * NPAD + c];
        if (c < NC) {
            g_cls[row * NC + c] = s + b_cls[c];
        } else {
            int cd = c - NC;
            float e = expf(s + b_det[cd]);
            if (cd < C) g_det[row * C + cd] = e;
            // 32 consecutive q -> distinct c within a warp (42 > 32): no RMW race
            scol[wid][cd] += e;
        }
    }
    __syncthreads();
    if (tid < NC) {
        float s = 0.f;
#pragma unroll
        for (int w = 0; w < 8; w++) s += scol[w][tid];
        g_colpart[blockIdx.x][tid] = s;
    }
}

// combine 64 column partials -> g_colsum
__global__ __launch_bounds__(672) void k_colfin() {
    int w = threadIdx.x >> 5;
    int lane = threadIdx.x & 31;
    if (w >= NC) return;
    float s = g_colpart[lane][w] + g_colpart[lane + 32][w];
#pragma unroll
    for (int o = 16; o > 0; o >>= 1) s += __shfl_down_sync(0xffffffff, s, o);
    if (lane == 0) g_colsum[w] = s;
}

// warp-per-row: scores = row_softmax(cls) * exp(det)/colsum; clip boxes; reset state
__global__ __launch_bounds__(256) void k_scores(const float* __restrict__ boxes) {
    const int gw   = (blockIdx.x * 256 + threadIdx.x) >> 5;  // row
    const int lane = threadIdx.x & 31;
    if (gw >= R) return;
    float e = 0.f;
    if (lane < NC) e = expf(g_cls[gw * NC + lane]);
    float s = e;
#pragma unroll
    for (int o = 16; o > 0; o >>= 1) s += __shfl_xor_sync(0xffffffff, s, o);
    float inv = 1.f / s;
    if (lane < C) {
        float sc = (e * inv) * g_det[gw * C + lane] / g_colsum[lane];
        g_scoresT[lane * R + gw] = sc;
        g_kept[gw * C + lane] = 0.f;
    }
    if (lane == 21) {
        float4 b = reinterpret_cast<const float4*>(boxes)[gw];
        g_bclip[gw] = make_float4(fminf(fmaxf(b.x, 0.f), IMG_W),
                                  fminf(fmaxf(b.y, 0.f), IMG_H),
                                  fminf(fmaxf(b.z, 0.f), IMG_W),
                                  fminf(fmaxf(b.w, 0.f), IMG_H));
    }
    if (gw == 0 && lane == 0) g_ncand = 0;
}

// per-class greedy NMS
__global__ __launch_bounds__(256) void k_nms() {
    __shared__ int scnt;
    __shared__ unsigned char ssupp[R];
    const int cls = blockIdx.x;
    const int tid = threadIdx.x;
    if (tid == 0) scnt = 0;
    __syncthreads();
    for (int r = tid; r < R; r += 256) {
        float v = g_scoresT[cls * R + r];
        if (v > SCORE_THRESH) {
            int p = atomicAdd(&scnt, 1);
            g_sidx[cls][p] = r;
            g_sval[cls][p] = v;
        }
    }
    __syncthreads();
    const int m = scnt;
    if (m == 0) return;
    for (int i = tid; i < m; i += 256) {
        float vi = g_sval[cls][i];
        int   ri = g_sidx[cls][i];
        int rank = 0;
        for (int j = 0; j < m; j++) {
            float vj = g_sval[cls][j];
            int   rj = g_sidx[cls][j];
            if (vj > vi || (vj == vi && rj < ri)) rank++;
        }
        g_sorder[cls][rank] = i;
    }
    for (int q = tid; q < m; q += 256) ssupp[q] = 0;
    __syncthreads();
    for (int pos = 0; pos < m; pos++) {
        if (!ssupp[pos]) {
            int   i = g_sorder[cls][pos];
            int   r = g_sidx[cls][i];
            float v = g_sval[cls][i];
            if (tid == 0) {
                g_kept[r * C + cls] = v;
                int p = atomicAdd(&g_ncand, 1);
                g_cand_val[p] = v;
                g_cand_idx[p] = r * C + cls;
            }
            float4 bi = g_bclip[r];
            for (int q = pos + 1 + tid; q < m; q += 256) {
                if (!ssupp[q]) {
                    int j = g_sorder[cls][q];
                    float4 bj = g_bclip[g_sidx[cls][j]];
                    if (iou_f(bi, bj) > NMS_THRESH) ssupp[q] = 1;
                }
            }
        }
        __syncthreads();
    }
}

// top-100 (jax.lax.top_k tie semantics) + parallel zero-fill
__global__ __launch_bounds__(256) void k_final(float* __restrict__ out) {
    __shared__ float bv[256];
    __shared__ int   bfi[256];
    __shared__ int   bps[256];
    __shared__ int   s_base;
    __shared__ int   s_woff[8];
    const int tid = threadIdx.x;
    int n = g_ncand;
    if (n > R * C) n = R * C;
    int take = n < TOPK ? n : TOPK;
    for (int round = 0; round < take; round++) {
        float best = -2.f; int bestfi = 0x7fffffff; int bestp = -1;
        for (int p = tid; p < n; p += 256) {
            float v = g_cand_val[p];
            if (v < 0.f) continue;
            int fi = g_cand_idx[p];
            if (v > best || (v == best && fi < bestfi)) {
                best = v; bestfi = fi; bestp = p;
            }
        }
        bv[tid] = best; bfi[tid] = bestfi; bps[tid] = bestp;
        __syncthreads();
        for (int s = 128; s > 0; s >>= 1) {
            if (tid < s) {
                if (bv[tid + s] > bv[tid] ||
                    (bv[tid + s] == bv[tid] && bfi[tid + s] < bfi[tid])) {
                    bv[tid] = bv[tid + s];
                    bfi[tid] = bfi[tid + s];
                    bps[tid] = bps[tid + s];
                }
            }
            __syncthreads();
        }
        if (tid == 0) {
            int fi = bfi[0];
            int prop = fi / C, cl = fi % C;
            float4 b = g_bclip[prop];
            out[round] = bv[0];
            out[TOPK + round * 4 + 0] = b.x;
            out[TOPK + round * 4 + 1] = b.y;
            out[TOPK + round * 4 + 2] = b.z;
            out[TOPK + round * 4 + 3] = b.w;
            out[TOPK + TOPK * 4 + round] = (float)cl;
            g_cand_val[bps[0]] = -1.f;
        }
        __syncthreads();
    }
    if (tid == 0) s_base = take;
    __syncthreads();
    for (int chunk = 0; chunk < R * C; chunk += 256) {
        if (s_base >= TOPK) break;
        int e = chunk + tid;
        bool f = (g_kept[e] == 0.f);
        unsigned bal = __ballot_sync(0xffffffff, f);
        if ((tid & 31) == 0) s_woff[tid >> 5] = __popc(bal);
        __syncthreads();
        int pre = 0;
#pragma unroll
        for (int w = 0; w < 8; w++)
            if (w < (tid >> 5)) pre += s_woff[w];
        int rank = pre + __popc(bal & ((1u << (tid & 31)) - 1u));
        int slot = s_base + rank;
        if (f && slot < TOPK) {
            int prop = e / C, cl = e % C;
            float4 b = g_bclip[prop];
            out[slot] = 0.f;
            out[TOPK + slot * 4 + 0] = b.x;
            out[TOPK + slot * 4 + 1] = b.y;
            out[TOPK + slot * 4 + 2] = b.z;
            out[TOPK + slot * 4 + 3] = b.w;
            out[TOPK + TOPK * 4 + slot] = (float)cl;
        }
        __syncthreads();
        if (tid == 0) {
            int tot = 0;
#pragma unroll
            for (int w = 0; w < 8; w++) tot += s_woff[w];
            s_base += tot;
            if (s_base > TOPK) s_base = TOPK;
        }
        __syncthreads();
    }
}

extern "C" void kernel_launch(void* const* d_in, const int* in_sizes, int n_in,
                              void* d_out, int out_size) {
    const float* x     = (const float*)d_in[0];
    const float* boxes = (const float*)d_in[1];
    const float* W_cls = (const float*)d_in[2];
    const float* b_cls = (const float*)d_in[3];
    const float* W_det = (const float*)d_in[4];
    const float* b_det = (const float*)d_in[5];
    float* out = (float*)d_out;

    static bool attr_set = false;
    if (!attr_set) {
        cudaFuncSetAttribute(k_gemm, cudaFuncAttributeMaxDynamicSharedMemorySize,
                             SM_TOTAL);
        attr_set = true;
    }

    k_prep<<<(NPAD * (D / 2) + 255) / 256, 256>>>(W_cls, W_det);
    dim3 gg(GRB, GKS);
    k_gemm<<<gg, GTH, SM_TOTAL>>>(x);
    k_reduce<<<64, 256>>>(b_cls, b_det);
    k_colfin<<<1, 672>>>();
    k_scores<<<R * 32 / 256, 256>>>(boxes);
    k_nms<<<C, 256>>>();
    k_final<<<1, 256>>>(out);
}